// round 4
// baseline (speedup 1.0000x reference)
#include <cuda_runtime.h>
#include <math.h>

#define B_ 64
#define T_ 256
#define F_ 64
#define U_ 512
#define G_ 2048            // 4*U
#define TB_ (T_*B_)        // 16384
#define NCTA 128

typedef unsigned long long ull;

// ---------------- device scratch ----------------
__device__ float g_xc[(size_t)TB_ * G_];      // x-contrib + bias  [t][b][4U]
__device__ float g_hseq[(size_t)TB_ * U_];    // h sequence        [t][b][U]
__device__ float g_hbufT[2][U_ * B_];         // ping-pong recurrent h, TRANSPOSED [u][b]
__device__ float g_cst_s[2][B_ * U_];         // saved final c (enc L0, enc L1)  [b][u]
__device__ float g_hst_s[2][B_ * U_];         // saved final h                   [b][u]
__device__ unsigned g_gen;
__device__ unsigned g_cnt;

// ---------------- f32x2 helpers (Blackwell packed fp32, 2x FFMA rate) ----------------
__device__ __forceinline__ void fma2(ull& d, ull a, ull b) {
    asm("fma.rn.f32x2 %0, %1, %2, %0;" : "+l"(d) : "l"(a), "l"(b));
}
__device__ __forceinline__ ull dup2(float x) {
    ull d; asm("mov.b64 %0, {%1, %1};" : "=l"(d) : "f"(x)); return d;
}
__device__ __forceinline__ float lo32(ull x) { return __uint_as_float((unsigned)x); }
__device__ __forceinline__ float hi32(ull x) { return __uint_as_float((unsigned)(x >> 32)); }

__device__ __forceinline__ unsigned smem_u32(const void* p) {
    return (unsigned)__cvta_generic_to_shared(p);
}

// ---------------- grid-wide barrier ----------------
__device__ __forceinline__ void grid_bar() {
    __syncthreads();
    if (threadIdx.x == 0) {
        __threadfence();
        unsigned my = *(volatile unsigned*)&g_gen;
        unsigned a = atomicAdd(&g_cnt, 1u);
        if (a == NCTA - 1u) {
            g_cnt = 0u;
            __threadfence();
            atomicExch(&g_gen, my + 1u);
        } else {
            while (*(volatile unsigned*)&g_gen == my) { __nanosleep(20); }
        }
        __threadfence();
    }
    __syncthreads();
}

__device__ __forceinline__ float sigf(float x) {
    return __fdividef(1.f, 1.f + __expf(-x));
}
__device__ __forceinline__ float tanhfast(float x) {
    float ax = fabsf(x);
    float e = __expf(2.f * ax);
    float t = 1.f - __fdividef(2.f, e + 1.f);
    return copysignf(t, x);
}

// ---------------- init transposed h buffer ----------------
__global__ void set_h(int sel) {
    int i = blockIdx.x * blockDim.x + threadIdx.x;   // i = u*64 + b
    if (i < B_ * U_) {
        int u = i >> 6, b = i & 63;
        float v = 0.f;
        if (sel == 1) v = g_hst_s[0][b * U_ + u];
        else if (sel == 2) v = g_hst_s[1][b * U_ + u];
        g_hbufT[0][i] = v;
    }
}

// ---------------- GEMM (f32x2): g_xc[m][n] = A[m][:K] @ W[K][2048] + bias[n] ----------------
// BM=64, BN=128, BK=16, 256 thr. Thread: 8 rows x 2 col-pairs.
__global__ void __launch_bounds__(256) gemm_bias(const float* __restrict__ A,
                                                 const float* __restrict__ W,
                                                 const float* __restrict__ bias,
                                                 int K, int permute, int a_sel) {
    __shared__ float As[64][16];
    __shared__ float Bs[16][128];
    const float* Ap = a_sel ? (const float*)g_hseq : A;
    const int tid = threadIdx.x;
    const int bm = blockIdx.y, bn = blockIdx.x;
    const int tr = tid >> 5, tc = tid & 31;

    ull acc[8][2];
#pragma unroll
    for (int i = 0; i < 8; i++) { acc[i][0] = 0ull; acc[i][1] = 0ull; }

    const int lr = tid >> 2;
    const int lq = (tid & 3) << 2;
    const int br = tid >> 5;
    const int bc = (tid & 31) << 2;
    const int rowg = bm * 64 + lr;
    const size_t abase = permute ? ((size_t)(rowg & 63) * T_ + (rowg >> 6)) * K
                                 : (size_t)rowg * K;

    for (int kt = 0; kt < K; kt += 16) {
        *(float4*)&As[lr][lq]     = *(const float4*)(Ap + abase + kt + lq);
        *(float4*)&Bs[br][bc]     = *(const float4*)(W + (size_t)(kt + br)     * G_ + bn * 128 + bc);
        *(float4*)&Bs[br + 8][bc] = *(const float4*)(W + (size_t)(kt + br + 8) * G_ + bn * 128 + bc);
        __syncthreads();
#pragma unroll
        for (int kk = 0; kk < 16; kk++) {
            ull b0 = *(const ull*)&Bs[kk][2 * tc];
            ull b1 = *(const ull*)&Bs[kk][2 * tc + 64];
#pragma unroll
            for (int i = 0; i < 8; i++) {
                ull ad = dup2(As[tr + 8 * i][kk]);   // warp-broadcast LDS + dup pack
                fma2(acc[i][0], ad, b0);
                fma2(acc[i][1], ad, b1);
            }
        }
        __syncthreads();
    }
    const int c0 = bn * 128 + 2 * tc;
    const float2 bz0 = *(const float2*)&bias[c0];
    const float2 bz1 = *(const float2*)&bias[c0 + 64];
#pragma unroll
    for (int i = 0; i < 8; i++) {
        int row = bm * 64 + tr + 8 * i;
        float2 v0 = make_float2(lo32(acc[i][0]) + bz0.x, hi32(acc[i][0]) + bz0.y);
        float2 v1 = make_float2(lo32(acc[i][1]) + bz1.x, hi32(acc[i][1]) + bz1.y);
        *(float2*)&g_xc[(size_t)row * G_ + c0]      = v0;
        *(float2*)&g_xc[(size_t)row * G_ + c0 + 64] = v1;
    }
}

// ---------------- persistent LSTM recurrence (f32x2) ----------------
// NCTA CTAs x 256 thr. CTA owns 4 units (16 gate cols c = gate*4 + uu).
// h_sh transposed: [512 u][68 pad], batches contiguous -> LDS.64 = batch pair.
// W2_sh: dup-packed float2 per (k, c). part: separate (NO aliasing).
// Compute role: ks = tid>>6, bgp = (tid&63)>>2, cg = tid&3.
// Broadcast double-buffered via cp.async halves to hide L2 latency.
#define H_STRIDE 68
#define SM_H_FLOATS (512 * H_STRIDE)            // 34816
#define SM_W2_FLOATS (512 * 32)                 // 16384
#define PART_CS 65
#define PART_KS (16 * PART_CS)                  // 1040
#define SM_PART_FLOATS (4 * PART_KS)            // 4160
#define REC_SMEM ((SM_H_FLOATS + SM_W2_FLOATS + SM_PART_FLOATS) * 4)  // 221440 B

__global__ void __launch_bounds__(256) lstm_rec(const float* __restrict__ Wh,
                                                int init_slot, int save_slot) {
    extern __shared__ float sm[];
    float* h_sh  = sm;                            // [512][68]
    float* W2_sh = sm + SM_H_FLOATS;              // [512][32]
    float* part  = W2_sh + SM_W2_FLOATS;          // [4][16][65]

    const int tid = threadIdx.x;
    const int u0 = blockIdx.x * 4;

    for (int e = tid; e < 512 * 16; e += 256) {
        int k = e >> 4, c = e & 15;
        int gcol = (c >> 2) * 512 + u0 + (c & 3);
        float w = Wh[(size_t)k * G_ + gcol];
        *(float2*)&W2_sh[k * 32 + c * 2] = make_float2(w, w);
    }

    const int ks = tid >> 6;
    const int rem = tid & 63;
    const int bgp = rem >> 2;
    const int cg = rem & 3;
    const int pb0 = 2 * bgp;
    const int pb1 = 2 * bgp + 32;

    const int be = tid >> 2, uu = tid & 3, u = u0 + uu;
    float cst = (init_slot >= 0) ? g_cst_s[init_slot][be * U_ + u] : 0.f;

    const unsigned hbase = smem_u32(h_sh);
    __syncthreads();

    int ph = 0;
    for (int t = 0; t < T_; t++) {
        // x-contrib prefetch
        const size_t xb = ((size_t)t * B_ + be) * G_ + u;
        float xg0 = g_xc[xb];
        float xg1 = g_xc[xb + 512];
        float xg2 = g_xc[xb + 1024];
        float xg3 = g_xc[xb + 1536];

        // broadcast h (straight copy, transposed layout) in two cp.async halves
        const float* src = g_hbufT[ph];
#pragma unroll
        for (int i = 0; i < 16; i++) {
            int e = i * 256 + tid;
            int row = e >> 4, seg = e & 15;
            asm volatile("cp.async.cg.shared.global [%0], [%1], 16;" ::
                "r"(hbase + row * (H_STRIDE * 4) + seg * 16),
                "l"(src + row * 64 + seg * 4));
        }
        asm volatile("cp.async.commit_group;");
#pragma unroll
        for (int i = 16; i < 32; i++) {
            int e = i * 256 + tid;
            int row = e >> 4, seg = e & 15;
            asm volatile("cp.async.cg.shared.global [%0], [%1], 16;" ::
                "r"(hbase + row * (H_STRIDE * 4) + seg * 16),
                "l"(src + row * 64 + seg * 4));
        }
        asm volatile("cp.async.commit_group;");

        ull a00 = 0, a01 = 0, a02 = 0, a03 = 0;
        ull a10 = 0, a11 = 0, a12 = 0, a13 = 0;

        // half A: rows 0..255 ready
        asm volatile("cp.async.wait_group 1;");
        __syncthreads();
        {
            const float* hr = h_sh + (ks * 64) * H_STRIDE;
            const float* wr = W2_sh + (ks * 64) * 32 + cg * 8;
#pragma unroll 4
            for (int kk = 0; kk < 64; kk++) {
                ull h0 = *(const ull*)(hr + pb0);
                ull h1 = *(const ull*)(hr + pb1);
                ull w0 = *(const ull*)(wr + 0);
                ull w1 = *(const ull*)(wr + 2);
                ull w2 = *(const ull*)(wr + 4);
                ull w3 = *(const ull*)(wr + 6);
                fma2(a00, h0, w0); fma2(a01, h0, w1); fma2(a02, h0, w2); fma2(a03, h0, w3);
                fma2(a10, h1, w0); fma2(a11, h1, w1); fma2(a12, h1, w2); fma2(a13, h1, w3);
                hr += H_STRIDE; wr += 32;
            }
        }
        // half B: rows 256..511
        asm volatile("cp.async.wait_group 0;");
        __syncthreads();
        {
            const float* hr = h_sh + (256 + ks * 64) * H_STRIDE;
            const float* wr = W2_sh + (256 + ks * 64) * 32 + cg * 8;
#pragma unroll 4
            for (int kk = 0; kk < 64; kk++) {
                ull h0 = *(const ull*)(hr + pb0);
                ull h1 = *(const ull*)(hr + pb1);
                ull w0 = *(const ull*)(wr + 0);
                ull w1 = *(const ull*)(wr + 2);
                ull w2 = *(const ull*)(wr + 4);
                ull w3 = *(const ull*)(wr + 6);
                fma2(a00, h0, w0); fma2(a01, h0, w1); fma2(a02, h0, w2); fma2(a03, h0, w3);
                fma2(a10, h1, w0); fma2(a11, h1, w1); fma2(a12, h1, w2); fma2(a13, h1, w3);
                hr += H_STRIDE; wr += 32;
            }
        }

        // write partials: part[ks][c][b] (padded rows, no bank conflict)
        {
            float* pb = part + ks * PART_KS + (cg * 4) * PART_CS;
            ull ar0[4] = {a00, a01, a02, a03};
            ull ar1[4] = {a10, a11, a12, a13};
#pragma unroll
            for (int j = 0; j < 4; j++) {
                pb[j * PART_CS + pb0]     = lo32(ar0[j]);
                pb[j * PART_CS + pb0 + 1] = hi32(ar0[j]);
                pb[j * PART_CS + pb1]     = lo32(ar1[j]);
                pb[j * PART_CS + pb1 + 1] = hi32(ar1[j]);
            }
        }
        __syncthreads();

        // elementwise LSTM update for (be, uu)
        float gi = xg0, gj = xg1, gf = xg2, go = xg3;
#pragma unroll
        for (int s = 0; s < 4; s++) {
            const float* pp = part + s * PART_KS + be;
            gi += pp[(0 + uu) * PART_CS];
            gj += pp[(4 + uu) * PART_CS];
            gf += pp[(8 + uu) * PART_CS];
            go += pp[(12 + uu) * PART_CS];
        }
        cst = sigf(gf + 1.0f) * cst + sigf(gi) * tanhfast(gj);
        float h = sigf(go) * tanhfast(cst);

        g_hbufT[ph ^ 1][u * 64 + be] = h;
        g_hseq[((size_t)t * B_ + be) * U_ + u] = h;
        if (t == T_ - 1 && save_slot >= 0) {
            g_cst_s[save_slot][be * U_ + u] = cst;
            g_hst_s[save_slot][be * U_ + u] = h;
        }
        grid_bar();
        ph ^= 1;
    }
}

// ---------------- projection + mask ----------------
#define PROJ_SMEM_FLOATS (512*64 + 512 + 256)
__global__ void __launch_bounds__(256) proj_kernel(const float* __restrict__ outW,
                                                   const float* __restrict__ outb,
                                                   const int* __restrict__ lens,
                                                   float* __restrict__ out) {
    extern __shared__ float ps[];
    float* Wsh = ps;
    float* hsh = Wsh + 512 * 64;
    float* pp  = hsh + 512;
    const int tid = threadIdx.x;
    for (int e = tid; e < 512 * 64; e += 256) Wsh[e] = outW[e];
    __syncthreads();
    const int f = tid & 63, ks = tid >> 6;
    for (int rr = 0; rr < 64; rr++) {
        int m = blockIdx.x * 64 + rr;
        if (tid < 128) ((float4*)hsh)[tid] = ((const float4*)(g_hseq + (size_t)m * U_))[tid];
        __syncthreads();
        float s = 0.f;
#pragma unroll 8
        for (int kk = 0; kk < 128; kk++) {
            int k = ks * 128 + kk;
            s += hsh[k] * Wsh[k * 64 + f];
        }
        pp[tid] = s;
        __syncthreads();
        if (tid < 64) {
            float v = pp[tid] + pp[64 + tid] + pp[128 + tid] + pp[192 + tid] + outb[tid];
            int t = m >> 6, b = m & 63;
            out[((size_t)b * T_ + t) * F_ + tid] = (t < lens[b]) ? v : 0.f;
        }
        __syncthreads();
    }
}

// ---------------- launch ----------------
extern "C" void kernel_launch(void* const* d_in, const int* in_sizes, int n_in,
                              void* d_out, int out_size) {
    const float* inputs  = (const float*)d_in[0];
    const float* targets = (const float*)d_in[1];
    const int*   lens    = (const int*)  d_in[2];
    const float* enc_W0  = (const float*)d_in[3];
    const float* enc_b0  = (const float*)d_in[4];
    const float* enc_W1  = (const float*)d_in[5];
    const float* enc_b1  = (const float*)d_in[6];
    const float* dec_W0  = (const float*)d_in[7];
    const float* dec_b0  = (const float*)d_in[8];
    const float* dec_W1  = (const float*)d_in[9];
    const float* dec_b1  = (const float*)d_in[10];
    const float* out_W   = (const float*)d_in[11];
    const float* out_b   = (const float*)d_in[12];

    const int PROJ_SMEM = PROJ_SMEM_FLOATS * 4;
    cudaFuncSetAttribute(lstm_rec, cudaFuncAttributeMaxDynamicSharedMemorySize, REC_SMEM);
    cudaFuncSetAttribute(proj_kernel, cudaFuncAttributeMaxDynamicSharedMemorySize, PROJ_SMEM);

    dim3 ggrid(16, 256);  // N/128, M/64

    // ---- encoder layer 0
    set_h<<<NCTA, 256>>>(0);
    gemm_bias<<<ggrid, 256>>>(inputs, enc_W0, enc_b0, F_, 1, 0);
    lstm_rec<<<NCTA, 256, REC_SMEM>>>(enc_W0 + (size_t)F_ * G_, -1, 0);
    // ---- encoder layer 1
    gemm_bias<<<ggrid, 256>>>(nullptr, enc_W1, enc_b1, U_, 0, 1);
    set_h<<<NCTA, 256>>>(0);
    lstm_rec<<<NCTA, 256, REC_SMEM>>>(enc_W1 + (size_t)U_ * G_, -1, 1);
    // ---- decoder layer 0 (init = enc L0 finals)
    gemm_bias<<<ggrid, 256>>>(targets, dec_W0, dec_b0, F_, 1, 0);
    set_h<<<NCTA, 256>>>(1);
    lstm_rec<<<NCTA, 256, REC_SMEM>>>(dec_W0 + (size_t)F_ * G_, 0, -1);
    // ---- decoder layer 1 (init = enc L1 finals)
    gemm_bias<<<ggrid, 256>>>(nullptr, dec_W1, dec_b1, U_, 0, 1);
    set_h<<<NCTA, 256>>>(2);
    lstm_rec<<<NCTA, 256, REC_SMEM>>>(dec_W1 + (size_t)U_ * G_, 1, -1);
    // ---- projection + mask
    proj_kernel<<<256, 256, PROJ_SMEM>>>(out_W, out_b, lens, (float*)d_out);
}